// round 10
// baseline (speedup 1.0000x reference)
#include <cuda_runtime.h>
#include <cuda_bf16.h>
#include <cstdint>

// ---------------- problem constants ----------------
#define NQ     128
#define DIM    512
#define NC     262144
#define KSEL   100

#define QSCALE   20.0f
#define ZTHRESH  3.1f       // adaptive filter: thresh = 3.1 * ||q||
#define CAP      8192

// ---------------- device scratch ----------------
__device__ __align__(16) uint32_t g_qs8[NQ * DIM / 4];
__device__ int      g_thresh[NQ];
__device__ unsigned g_cnt[NQ * 32];
__device__ unsigned g_list[(size_t)NQ * CAP];

// ---------------- helpers ----------------
__device__ __forceinline__ uint32_t smem_u32(const void* p) {
    uint32_t a;
    asm("{ .reg .u64 t; cvta.to.shared.u64 t, %1; cvt.u32.u64 %0, t; }" : "=r"(a) : "l"(p));
    return a;
}
__device__ __forceinline__ unsigned f2ord(float f) {
    unsigned u = __float_as_uint(f);
    return (u & 0x80000000u) ? ~u : (u | 0x80000000u);
}
__device__ __forceinline__ float ord2f(unsigned u) {
    unsigned b = (u & 0x80000000u) ? (u ^ 0x80000000u) : ~u;
    return __uint_as_float(b);
}
__device__ __forceinline__ uint32_t quant4(float4 v) {
    int i0 = __float2int_rn(v.x * QSCALE);
    int i1 = __float2int_rn(v.y * QSCALE);
    int i2 = __float2int_rn(v.z * QSCALE);
    int i3 = __float2int_rn(v.w * QSCALE);
    uint32_t t, r;
    asm("cvt.pack.sat.s8.s32.b32 %0, %1, %2, %3;" : "=r"(t) : "r"(i3), "r"(i2), "r"(0));
    asm("cvt.pack.sat.s8.s32.b32 %0, %1, %2, %3;" : "=r"(r) : "r"(i1), "r"(i0), "r"(t));
    return r;
}
__device__ __forceinline__ void cpa16(uint32_t dst, const void* src) {
    asm volatile("cp.async.ca.shared.global [%0], [%1], 16;" :: "r"(dst), "l"(src));
}
#define CP_COMMIT() asm volatile("cp.async.commit_group;" ::: "memory")
#define CP_WAIT(n)  asm volatile("cp.async.wait_group %0;" :: "n"(n) : "memory")

#define LDMX4(r0, r1, r2, r3, addr) \
    asm volatile("ldmatrix.sync.aligned.m8n8.x4.shared.b16 {%0,%1,%2,%3}, [%4];" \
                 : "=r"(r0), "=r"(r1), "=r"(r2), "=r"(r3) : "r"(addr))

__device__ __forceinline__ void imma16832(int* d, const uint32_t* a, const uint32_t* b) {
    asm volatile(
        "mma.sync.aligned.m16n8k32.row.col.s32.s8.s8.s32 "
        "{%0,%1,%2,%3}, {%4,%5,%6,%7}, {%8,%9}, {%0,%1,%2,%3};"
        : "+r"(d[0]), "+r"(d[1]), "+r"(d[2]), "+r"(d[3])
        : "r"(a[0]), "r"(a[1]), "r"(a[2]), "r"(a[3]), "r"(b[0]), "r"(b[1]));
}

// ============================================================
// Kernel 0: Q fp32 -> int8, adaptive thresholds, zero counters
// ============================================================
__global__ void qconv_kernel(const float* __restrict__ Q) {
    int i = blockIdx.x * blockDim.x + threadIdx.x;
    if (i < NQ * DIM / 4)
        g_qs8[i] = quant4(*(const float4*)(Q + i * 4));
    if (i < NQ) {
        g_cnt[i * 32] = 0u;
        const float* qr = Q + i * DIM;
        float ns = 0.f;
#pragma unroll 8
        for (int k = 0; k < DIM; k++) ns = fmaf(qr[k], qr[k], ns);
        g_thresh[i] = (int)(ZTHRESH * sqrtf(ns) * QSCALE * QSCALE);
    }
}

// ============================================================
// Kernel 1: fused conv+GEMM.
// fp32 C chunks stream via cp.async into smem, quantized in-thread
// (each thread converts exactly the bytes it copied), IMMA on int8.
// BM=128 (A resident), BN=128, BK=64. 1 CTA/SM.
// ============================================================
#define APITCH   528
#define ASM_B    (128 * APITCH)             // 67584
#define FPITCH   272                        // fp32 stage pitch (256B data + pad)
#define FBUF     (128 * FPITCH)             // 34816
#define BPITCH   80
#define BSB      (128 * BPITCH)             // 10240
#define GSMEM    (ASM_B + 2 * FBUF + 2 * BSB)  // 157696

__global__ __launch_bounds__(256, 1) void gemm_kernel(const float* __restrict__ C) {
    extern __shared__ __align__(16) uint8_t sm[];
    __shared__ int sth[128];

    const int tid  = threadIdx.x;
    const int lane = tid & 31;
    const int wn   = tid >> 5;
    const size_t nb = (size_t)blockIdx.x * 128;

    const uint32_t asm0 = smem_u32(sm);
    const uint32_t f0   = asm0 + ASM_B;
    const uint32_t b0   = f0 + 2 * FBUF;

    if (tid < 128) sth[tid] = g_thresh[tid];

    // per-thread convert/copy region: row = tid>>1, half = tid&1 (32 floats)
    const int crow = tid >> 1, chalf = tid & 1;

    auto issueA = [&]() {
#pragma unroll
        for (int i = 0; i < 16; i++) {
            int idx = tid + i * 256;
            int row = idx >> 5, c16 = idx & 31;
            cpa16(asm0 + row * APITCH + c16 * 16,
                  (const uint8_t*)g_qs8 + row * 512 + c16 * 16);
        }
    };
    auto issueF = [&](int c, int s) {   // fp32 chunk c -> fbuf slot s
        const float* src = C + (size_t)(nb + crow) * DIM + c * 64 + chalf * 32;
        uint32_t dst = f0 + s * FBUF + crow * FPITCH + chalf * 128;
#pragma unroll
        for (int i = 0; i < 8; i++) cpa16(dst + i * 16, src + i * 4);
    };
    auto convert = [&](int s) {         // fbuf slot s -> int8 Bs slot s
        uint8_t* fsrc = sm + ASM_B + s * FBUF + crow * FPITCH + chalf * 128;
        uint32_t q[8];
#pragma unroll
        for (int i = 0; i < 8; i++)
            q[i] = quant4(*(const float4*)(fsrc + i * 16));
        uint8_t* bdst = sm + ASM_B + 2 * FBUF + s * BSB + crow * BPITCH + chalf * 32;
        *(uint4*)(bdst)      = make_uint4(q[0], q[1], q[2], q[3]);
        *(uint4*)(bdst + 16) = make_uint4(q[4], q[5], q[6], q[7]);
    };

    int acc[8][2][4];
#pragma unroll
    for (int i = 0; i < 8; i++)
#pragma unroll
        for (int j = 0; j < 2; j++)
#pragma unroll
            for (int r = 0; r < 4; r++) acc[i][j][r] = 0;

    // prologue: G0 = {A, F0}, G1 = {F1}
    issueA(); issueF(0, 0); CP_COMMIT();
    issueF(1, 1); CP_COMMIT();
    CP_WAIT(1);             // A + F0 arrived
    convert(0);
    __syncthreads();        // A + Bs[0] visible to all

    const int g2 = lane >> 3, r = lane & 7;

#pragma unroll
    for (int c = 0; c < 8; c++) {
        // ---- compute chunk c (IMMA issues early; tensor pipe drains ~2K cyc) ----
        const uint32_t bb = b0 + (c & 1) * BSB;
#pragma unroll
        for (int kk = 0; kk < 2; kk++) {
            uint32_t bf0, bf1, bf2, bf3;
            {
                int row = wn * 16 + (g2 >> 1) * 8 + r;
                int seg = kk * 2 + (g2 & 1);
                LDMX4(bf0, bf1, bf2, bf3, bb + row * BPITCH + seg * 16);
            }
            uint32_t bn0[2] = { bf0, bf1 }, bn1[2] = { bf2, bf3 };
#pragma unroll
            for (int mt = 0; mt < 8; mt++) {
                uint32_t a[4];
                int row = mt * 16 + (g2 & 1) * 8 + r;
                int seg = kk * 2 + (g2 >> 1);
                LDMX4(a[0], a[1], a[2], a[3],
                      asm0 + row * APITCH + c * 64 + seg * 16);
                imma16832(acc[mt][0], a, bn0);
                imma16832(acc[mt][1], a, bn1);
            }
        }
        // ---- overlap: stream chunk c+2, convert chunk c+1 ----
        if (c + 1 < 8) {
            if (c + 2 < 8) { issueF(c + 2, c & 1); CP_COMMIT(); CP_WAIT(1); }
            else           { CP_WAIT(0); }
            convert((c + 1) & 1);
        }
        __syncthreads();    // Bs[(c+1)&1] stores visible; Bs[c&1] safe to reuse next
    }

    // adaptive filter epilogue
#pragma unroll
    for (int mt = 0; mt < 8; mt++)
#pragma unroll
        for (int nt = 0; nt < 2; nt++)
#pragma unroll
            for (int rr = 0; rr < 4; rr++) {
                int m = mt * 16 + (lane >> 2) + (rr >> 1) * 8;
                if (acc[mt][nt][rr] >= sth[m]) {
                    unsigned n = (unsigned)(nb + wn * 16 + nt * 8 + (lane & 3) * 2 + (rr & 1));
                    unsigned pos = atomicAdd(&g_cnt[m * 32], 1u);
                    if (pos < CAP) g_list[(size_t)m * CAP + pos] = n;
                }
            }
}

// ============================================================
// Kernel 2: exact sequential rescore (8-deep explicit prefetch) + sort
// ============================================================
#define RT_THREADS 256
#define RT_SMEM (CAP * 8 + DIM * 4)

__global__ __launch_bounds__(RT_THREADS) void rescore_kernel(const float* __restrict__ Q,
                                                             const float* __restrict__ C,
                                                             float* __restrict__ out,
                                                             int out_elems) {
    extern __shared__ __align__(16) uint8_t tsm[];
    unsigned long long* keys = (unsigned long long*)tsm;
    float* qrow = (float*)(tsm + CAP * 8);

    const int q = blockIdx.x, tid = threadIdx.x;
    for (int i = tid; i < DIM; i += RT_THREADS) qrow[i] = Q[q * DIM + i];
    __syncthreads();

    unsigned cnt = min(g_cnt[q * 32], (unsigned)CAP);

    for (unsigned j = tid; j < cnt; j += RT_THREADS) {
        unsigned ci = g_list[(size_t)q * CAP + j];
        const float4* cv = (const float4*)(C + (size_t)ci * DIM);
        float4 buf[8];
#pragma unroll
        for (int i = 0; i < 8; i++) buf[i] = cv[i];
        float acc = 0.f;
#pragma unroll
        for (int g = 0; g < 16; g++) {
            float4 nxt[8];
            if (g < 15) {
#pragma unroll
                for (int i = 0; i < 8; i++) nxt[i] = cv[(g + 1) * 8 + i];
            }
#pragma unroll
            for (int i = 0; i < 8; i++) {
                const int k = g * 32 + i * 4;
                acc = fmaf(qrow[k + 0], buf[i].x, acc);
                acc = fmaf(qrow[k + 1], buf[i].y, acc);
                acc = fmaf(qrow[k + 2], buf[i].z, acc);
                acc = fmaf(qrow[k + 3], buf[i].w, acc);
            }
#pragma unroll
            for (int i = 0; i < 8; i++) buf[i] = nxt[i];
        }
        keys[j] = ((unsigned long long)f2ord(acc) << 32) | (unsigned long long)(~ci);
    }
    __syncthreads();

    unsigned n = 1; while (n < cnt) n <<= 1; if (n < 2) n = 2;
    for (unsigned i = cnt + tid; i < n; i += RT_THREADS) keys[i] = 0ull;
    __syncthreads();

    for (unsigned ks = 2; ks <= n; ks <<= 1) {
        for (unsigned st = ks >> 1; st > 0; st >>= 1) {
            for (unsigned i = tid; i < n; i += RT_THREADS) {
                unsigned ix = i ^ st;
                if (ix > i) {
                    unsigned long long a = keys[i], b = keys[ix];
                    bool desc = ((i & ks) == 0);
                    if ((a < b) == desc) { keys[i] = b; keys[ix] = a; }
                }
            }
            __syncthreads();
        }
    }

    for (int j = tid; j < KSEL; j += RT_THREADS) {
        unsigned long long ky = keys[j];
        unsigned u = (unsigned)(ky >> 32);
        unsigned idx = ~((unsigned)ky);
        out[q * KSEL + j] = ord2f(u);
        if (out_elems >= 2 * NQ * KSEL)
            out[NQ * KSEL + q * KSEL + j] = (float)idx;
    }
}

// ---------------- launch ----------------
extern "C" void kernel_launch(void* const* d_in, const int* in_sizes, int n_in,
                              void* d_out, int out_size)
{
    const float* Q = (const float*)d_in[0];
    const float* C = (const float*)d_in[1];
    float* out = (float*)d_out;

    cudaFuncSetAttribute(gemm_kernel,    cudaFuncAttributeMaxDynamicSharedMemorySize, GSMEM);
    cudaFuncSetAttribute(rescore_kernel, cudaFuncAttributeMaxDynamicSharedMemorySize, RT_SMEM);

    qconv_kernel<<<64, 256>>>(Q);
    gemm_kernel<<<NC / 128, 256, GSMEM>>>(C);
    rescore_kernel<<<NQ, RT_THREADS, RT_SMEM>>>(Q, C, out, out_size);
}

// round 11
// speedup vs baseline: 1.1309x; 1.1309x over previous
#include <cuda_runtime.h>
#include <cuda_bf16.h>
#include <cstdint>

// ---------------- problem constants ----------------
#define NQ     128
#define DIM    512
#define NC     262144
#define KSEL   100

#define QSCALE   20.0f      // int8 quantization scale
#define ZTHRESH  3.1f       // adaptive filter: thresh = 3.1 * ||q|| (survivors ~254/q)
#define CAP      8192       // per-query survivor capacity

// ---------------- device scratch ----------------
__device__ __align__(16) uint32_t g_qs8[NQ * DIM / 4];    // int8 queries packed
__device__ __align__(16) int8_t   g_c8[(size_t)NC * DIM]; // int8 candidates (128MB)
__device__ int      g_thresh[NQ];
__device__ unsigned g_cnt[NQ * 32];
__device__ unsigned g_list[(size_t)NQ * CAP];

// ---------------- helpers ----------------
__device__ __forceinline__ uint32_t smem_u32(const void* p) {
    uint32_t a;
    asm("{ .reg .u64 t; cvta.to.shared.u64 t, %1; cvt.u32.u64 %0, t; }" : "=r"(a) : "l"(p));
    return a;
}
__device__ __forceinline__ unsigned f2ord(float f) {
    unsigned u = __float_as_uint(f);
    return (u & 0x80000000u) ? ~u : (u | 0x80000000u);
}
__device__ __forceinline__ float ord2f(unsigned u) {
    unsigned b = (u & 0x80000000u) ? (u ^ 0x80000000u) : ~u;
    return __uint_as_float(b);
}
__device__ __forceinline__ uint32_t quant4(float4 v) {
    int i0 = __float2int_rn(v.x * QSCALE);
    int i1 = __float2int_rn(v.y * QSCALE);
    int i2 = __float2int_rn(v.z * QSCALE);
    int i3 = __float2int_rn(v.w * QSCALE);
    uint32_t t, r;
    asm("cvt.pack.sat.s8.s32.b32 %0, %1, %2, %3;" : "=r"(t) : "r"(i3), "r"(i2), "r"(0));
    asm("cvt.pack.sat.s8.s32.b32 %0, %1, %2, %3;" : "=r"(r) : "r"(i1), "r"(i0), "r"(t));
    return r;
}
__device__ __forceinline__ void cpa16(uint32_t dst, const void* src) {
    asm volatile("cp.async.ca.shared.global [%0], [%1], 16;" :: "r"(dst), "l"(src));
}
#define CP_COMMIT() asm volatile("cp.async.commit_group;" ::: "memory")
#define CP_WAIT(n)  asm volatile("cp.async.wait_group %0;" :: "n"(n) : "memory")

#define LDMX4(r0, r1, r2, r3, addr) \
    asm volatile("ldmatrix.sync.aligned.m8n8.x4.shared.b16 {%0,%1,%2,%3}, [%4];" \
                 : "=r"(r0), "=r"(r1), "=r"(r2), "=r"(r3) : "r"(addr))

__device__ __forceinline__ void imma16832(int* d, const uint32_t* a, const uint32_t* b) {
    asm volatile(
        "mma.sync.aligned.m16n8k32.row.col.s32.s8.s8.s32 "
        "{%0,%1,%2,%3}, {%4,%5,%6,%7}, {%8,%9}, {%0,%1,%2,%3};"
        : "+r"(d[0]), "+r"(d[1]), "+r"(d[2]), "+r"(d[3])
        : "r"(a[0]), "r"(a[1]), "r"(a[2]), "r"(a[3]), "r"(b[0]), "r"(b[1]));
}

// ============================================================
// Kernel 0a: Q fp32 -> int8 + warp-parallel norms -> thresholds
// ============================================================
__global__ void qconv_kernel(const float* __restrict__ Q) {
    int i = blockIdx.x * blockDim.x + threadIdx.x;
    if (i < NQ * DIM / 4)
        g_qs8[i] = quant4(*(const float4*)(Q + i * 4));
    int gw = i >> 5, lane = i & 31;
    if (gw < NQ) {
        const float* qr = Q + gw * DIM;
        float ns = 0.f;
#pragma unroll
        for (int t = 0; t < 4; t++) {
            float4 v = *(const float4*)(qr + lane * 4 + t * 128);
            ns += v.x * v.x + v.y * v.y + v.z * v.z + v.w * v.w;
        }
#pragma unroll
        for (int o = 16; o > 0; o >>= 1) ns += __shfl_xor_sync(0xFFFFFFFFu, ns, o);
        if (lane == 0) {
            g_thresh[gw] = (int)(ZTHRESH * sqrtf(ns) * QSCALE * QSCALE);
            g_cnt[gw * 32] = 0u;
        }
    }
}

// ============================================================
// Kernel 0b: C fp32 -> int8 (bandwidth-bound)
// ============================================================
__global__ __launch_bounds__(512) void cconv_kernel(const float* __restrict__ C) {
    size_t t = (size_t)blockIdx.x * blockDim.x + threadIdx.x;
    const float* src = C + t * 16;
    uint4 o;
    o.x = quant4(*(const float4*)(src + 0));
    o.y = quant4(*(const float4*)(src + 4));
    o.z = quant4(*(const float4*)(src + 8));
    o.w = quant4(*(const float4*)(src + 12));
    *(uint4*)(g_c8 + t * 16) = o;
}

// ============================================================
// Kernel 1: int8 IMMA GEMM, 3-stage cp.async pipeline, adaptive filter
// (identical to round-9: ~250us, mma-pipe floor)
// ============================================================
#define APITCH   528
#define ASM_B    (128 * APITCH)             // 67584
#define BPITCH   80
#define BSTAGE   (128 * BPITCH)             // 10240
#define GSMEM    (ASM_B + 3 * BSTAGE)       // 98304

__global__ __launch_bounds__(256, 2) void gemm_kernel() {
    extern __shared__ __align__(16) uint8_t sm[];
    __shared__ int sth[128];

    const int tid  = threadIdx.x;
    const int lane = tid & 31;
    const int wn   = tid >> 5;
    const size_t nb = (size_t)blockIdx.x * 128;

    const uint32_t asm0 = smem_u32(sm);
    const uint32_t bsm0 = asm0 + ASM_B;

    if (tid < 128) sth[tid] = g_thresh[tid];

    auto issueA = [&]() {
#pragma unroll
        for (int i = 0; i < 16; i++) {
            int idx = tid + i * 256;
            int row = idx >> 5, c16 = idx & 31;
            cpa16(asm0 + row * APITCH + c16 * 16,
                  (const uint8_t*)g_qs8 + row * 512 + c16 * 16);
        }
    };
    auto issueB = [&](int c, int s) {
#pragma unroll
        for (int i = 0; i < 2; i++) {
            int idx = tid + i * 256;
            int row = idx >> 2, seg = idx & 3;
            cpa16(bsm0 + s * BSTAGE + row * BPITCH + seg * 16,
                  g_c8 + (nb + row) * 512 + c * 64 + seg * 16);
        }
    };

    int acc[8][2][4];
#pragma unroll
    for (int i = 0; i < 8; i++)
#pragma unroll
        for (int j = 0; j < 2; j++)
#pragma unroll
            for (int r = 0; r < 4; r++) acc[i][j][r] = 0;

    issueA(); issueB(0, 0); CP_COMMIT();
    issueB(1, 1); CP_COMMIT();

    const int g2 = lane >> 3, r = lane & 7;

#pragma unroll
    for (int c = 0; c < 8; c++) {
        __syncthreads();
        if (c + 2 < 8) { issueB(c + 2, (c + 2) % 3); CP_COMMIT(); }
        if (c < 6)       CP_WAIT(2);
        else if (c == 6) CP_WAIT(1);
        else             CP_WAIT(0);
        __syncthreads();

        const uint32_t bb = bsm0 + (c % 3) * BSTAGE;
#pragma unroll
        for (int kk = 0; kk < 2; kk++) {
            uint32_t b0, b1, b2, b3;
            {
                int row = wn * 16 + (g2 >> 1) * 8 + r;
                int seg = kk * 2 + (g2 & 1);
                LDMX4(b0, b1, b2, b3, bb + row * BPITCH + seg * 16);
            }
            uint32_t bn0[2] = { b0, b1 }, bn1[2] = { b2, b3 };
#pragma unroll
            for (int mt = 0; mt < 8; mt++) {
                uint32_t a[4];
                int row = mt * 16 + (g2 & 1) * 8 + r;
                int seg = kk * 2 + (g2 >> 1);
                LDMX4(a[0], a[1], a[2], a[3],
                      asm0 + row * APITCH + c * 64 + seg * 16);
                imma16832(acc[mt][0], a, bn0);
                imma16832(acc[mt][1], a, bn1);
            }
        }
    }

    // adaptive filter epilogue
#pragma unroll
    for (int mt = 0; mt < 8; mt++)
#pragma unroll
        for (int nt = 0; nt < 2; nt++)
#pragma unroll
            for (int rr = 0; rr < 4; rr++) {
                int m = mt * 16 + (lane >> 2) + (rr >> 1) * 8;
                if (acc[mt][nt][rr] >= sth[m]) {
                    unsigned n = (unsigned)(nb + wn * 16 + nt * 8 + (lane & 3) * 2 + (rr & 1));
                    unsigned pos = atomicAdd(&g_cnt[m * 32], 1u);
                    if (pos < CAP) g_list[(size_t)m * CAP + pos] = n;
                }
            }
}

// ============================================================
// Kernel 2: exact sequential rescore (8x float4 double-buffer prefetch)
// + bitonic sort. fmaf chain order == reference => bit-exact.
// ============================================================
#define RT_THREADS 256
#define RT_SMEM (CAP * 8 + DIM * 4)

__global__ __launch_bounds__(RT_THREADS) void rescore_kernel(const float* __restrict__ Q,
                                                             const float* __restrict__ C,
                                                             float* __restrict__ out,
                                                             int out_elems) {
    extern __shared__ __align__(16) uint8_t tsm[];
    unsigned long long* keys = (unsigned long long*)tsm;
    float* qrow = (float*)(tsm + CAP * 8);

    const int q = blockIdx.x, tid = threadIdx.x;
    for (int i = tid; i < DIM; i += RT_THREADS) qrow[i] = Q[q * DIM + i];
    __syncthreads();

    unsigned cnt = min(g_cnt[q * 32], (unsigned)CAP);

    for (unsigned j = tid; j < cnt; j += RT_THREADS) {
        unsigned ci = g_list[(size_t)q * CAP + j];
        const float4* cv = (const float4*)(C + (size_t)ci * DIM);
        float4 buf[8];
#pragma unroll
        for (int i = 0; i < 8; i++) buf[i] = cv[i];
        float acc = 0.f;
#pragma unroll
        for (int g = 0; g < 16; g++) {
            float4 nxt[8];
            if (g < 15) {
#pragma unroll
                for (int i = 0; i < 8; i++) nxt[i] = cv[(g + 1) * 8 + i];
            }
#pragma unroll
            for (int i = 0; i < 8; i++) {
                const int k = g * 32 + i * 4;
                acc = fmaf(qrow[k + 0], buf[i].x, acc);
                acc = fmaf(qrow[k + 1], buf[i].y, acc);
                acc = fmaf(qrow[k + 2], buf[i].z, acc);
                acc = fmaf(qrow[k + 3], buf[i].w, acc);
            }
#pragma unroll
            for (int i = 0; i < 8; i++) buf[i] = nxt[i];
        }
        keys[j] = ((unsigned long long)f2ord(acc) << 32) | (unsigned long long)(~ci);
    }
    __syncthreads();

    unsigned n = 1; while (n < cnt) n <<= 1; if (n < 2) n = 2;
    for (unsigned i = cnt + tid; i < n; i += RT_THREADS) keys[i] = 0ull;
    __syncthreads();

    for (unsigned ks = 2; ks <= n; ks <<= 1) {
        for (unsigned st = ks >> 1; st > 0; st >>= 1) {
            for (unsigned i = tid; i < n; i += RT_THREADS) {
                unsigned ix = i ^ st;
                if (ix > i) {
                    unsigned long long a = keys[i], b = keys[ix];
                    bool desc = ((i & ks) == 0);
                    if ((a < b) == desc) { keys[i] = b; keys[ix] = a; }
                }
            }
            __syncthreads();
        }
    }

    for (int j = tid; j < KSEL; j += RT_THREADS) {
        unsigned long long ky = keys[j];
        unsigned u = (unsigned)(ky >> 32);
        unsigned idx = ~((unsigned)ky);
        out[q * KSEL + j] = ord2f(u);
        if (out_elems >= 2 * NQ * KSEL)
            out[NQ * KSEL + q * KSEL + j] = (float)idx;
    }
}

// ---------------- launch ----------------
extern "C" void kernel_launch(void* const* d_in, const int* in_sizes, int n_in,
                              void* d_out, int out_size)
{
    const float* Q = (const float*)d_in[0];
    const float* C = (const float*)d_in[1];
    float* out = (float*)d_out;

    cudaFuncSetAttribute(gemm_kernel,    cudaFuncAttributeMaxDynamicSharedMemorySize, GSMEM);
    cudaFuncSetAttribute(rescore_kernel, cudaFuncAttributeMaxDynamicSharedMemorySize, RT_SMEM);

    qconv_kernel<<<64, 256>>>(Q);
    cconv_kernel<<<(int)((size_t)NC * DIM / 16 / 512), 512>>>(C);
    gemm_kernel<<<NC / 128, 256, GSMEM>>>();
    rescore_kernel<<<NQ, RT_THREADS, RT_SMEM>>>(Q, C, out, out_size);
}